// round 9
// baseline (speedup 1.0000x reference)
#include <cuda_runtime.h>
#include <cstdint>

#define NPTS 8192
#define NS   2048
#define NK   32
#define NB   4
#define MPB  65536              /* NK*NS per batch */
#define FSZ  (NB*64*MPB)        /* 16.7M floats per feature buffer */
#define NPB  1024               /* stats partial blocks (4*256) */

__device__ float g_y0[FSZ];
__device__ float g_t1[FSZ];
__device__ float g_t2[FSZ];
__device__ float g_x1[FSZ];
__device__ float g_nxyz[NB*NS*3];
__device__ int   g_idx[NB*NK*NS];
__device__ float g_ps[64*2048];
__device__ float g_pq[64*2048];
__device__ float g_aff[5*128];

static __device__ __forceinline__ unsigned long long pk2(float lo, float hi){
    unsigned long long r; asm("mov.b64 %0,{%1,%2};" : "=l"(r) : "f"(lo), "f"(hi)); return r;
}
static __device__ __forceinline__ void upk2(unsigned long long v, float& lo, float& hi){
    asm("mov.b64 {%0,%1},%2;" : "=f"(lo), "=f"(hi) : "l"(v));
}
static __device__ __forceinline__ void upk2u(unsigned long long v, unsigned& lo, unsigned& hi){
    asm("mov.b64 {%0,%1},%2;" : "=r"(lo), "=r"(hi) : "l"(v));
}
static __device__ __forceinline__ unsigned long long f2fma(unsigned long long a, unsigned long long b, unsigned long long c){
    unsigned long long r; asm("fma.rn.f32x2 %0,%1,%2,%3;" : "=l"(r) : "l"(a), "l"(b), "l"(c)); return r;
}
static __device__ __forceinline__ unsigned long long f2mul(unsigned long long a, unsigned long long b){
    unsigned long long r; asm("mul.rn.f32x2 %0,%1,%2;" : "=l"(r) : "l"(a), "l"(b)); return r;
}
static __device__ __forceinline__ unsigned long long f2add(unsigned long long a, unsigned long long b){
    unsigned long long r; asm("add.rn.f32x2 %0,%1,%2;" : "=l"(r) : "l"(a), "l"(b)); return r;
}
static __device__ __forceinline__ unsigned long long f2sub(unsigned long long a, unsigned long long b){
    unsigned long long r; asm("sub.rn.f32x2 %0,%1,%2;" : "=l"(r) : "l"(a), "l"(b)); return r;
}

// ---------------- FPS v4: spatial-sort + exact-safe group pruning ----------------
// Points counting-sorted into 8x8x8 cells (one-time). Each thread owns 16
// consecutive sorted points (spatially local). Per iteration, a conservative
// bound test skips the whole group when min(dist, d_new) is provably a no-op
// for every member -> outputs bit-identical to the unpruned kernel.
// Distance chain for computed groups: exact sub/mul/add rounding (unchanged).
// First-occurrence argmax via (orig<<13|sorted) packs + atomicMin.
extern __shared__ float4 spts[];    // 8192 sorted points, .w = orig index bits

__global__ __launch_bounds__(512, 1) void fps_kernel(const float* __restrict__ xyz,
                                                     float* __restrict__ outxyz,
                                                     float* __restrict__ nxyz)
{
    int b = blockIdx.x, tid = threadIdx.x;
    int lane = tid & 31, wid = tid >> 5;     // 16 warps
    const float* X = xyz + (size_t)b * 3 * NPTS;

    __shared__ unsigned swm[32];
    __shared__ int swin[2];
    __shared__ int hist[512];
    __shared__ int wsum[16];

    hist[tid < 512 ? tid : 0] = 0;
    if (tid < 2) swin[tid] = 0x7fffffff;
    if (tid >= 16 && tid < 32) swm[tid] = 0u;
    __syncthreads();

    // pass 1: cell counts
#pragma unroll 4
    for (int j = 0; j < 16; ++j) {
        int n = tid + j * 512;
        float x = X[n], y = X[NPTS + n], z = X[2*NPTS + n];
        int cell = min(7, (int)(x * 8.f)) + 8 * min(7, (int)(y * 8.f))
                 + 64 * min(7, (int)(z * 8.f));
        atomicAdd(&hist[cell], 1);
    }
    __syncthreads();

    // exclusive scan of hist[512]
    int v = hist[tid];
    int inc = v;
#pragma unroll
    for (int off = 1; off < 32; off <<= 1) {
        int o = __shfl_up_sync(0xffffffffu, inc, off);
        if (lane >= off) inc += o;
    }
    if (lane == 31) wsum[wid] = inc;
    __syncthreads();
    if (wid == 0) {
        int s = (lane < 16) ? wsum[lane] : 0;
#pragma unroll
        for (int off = 1; off < 16; off <<= 1) {
            int o = __shfl_up_sync(0xffffffffu, s, off);
            if (lane >= off) s += o;
        }
        if (lane < 16) wsum[lane] = s;
    }
    __syncthreads();
    int wbase = (wid > 0) ? wsum[wid - 1] : 0;
    hist[tid] = wbase + inc - v;               // exclusive start, becomes running
    __syncthreads();

    // pass 2: scatter into sorted smem mirror
#pragma unroll 4
    for (int j = 0; j < 16; ++j) {
        int n = tid + j * 512;
        float x = X[n], y = X[NPTS + n], z = X[2*NPTS + n];
        int cell = min(7, (int)(x * 8.f)) + 8 * min(7, (int)(y * 8.f))
                 + 64 * min(7, (int)(z * 8.f));
        int pos = atomicAdd(&hist[cell], 1);
        spts[pos] = make_float4(x, y, z, __int_as_float(n));
    }
    __syncthreads();

    // load my 16 sorted points; centroid + conservative radius
    unsigned long long x2[8], y2[8], z2[8];
    unsigned dist[16];
    int oidx[16];
    float gx = 0.f, gy = 0.f, gz = 0.f;
#pragma unroll
    for (int p = 0; p < 8; ++p) {
        float4 A = spts[tid * 16 + 2*p];
        float4 B = spts[tid * 16 + 2*p + 1];
        x2[p] = pk2(A.x, B.x); y2[p] = pk2(A.y, B.y); z2[p] = pk2(A.z, B.z);
        oidx[2*p] = __float_as_int(A.w); oidx[2*p+1] = __float_as_int(B.w);
        gx += A.x + B.x; gy += A.y + B.y; gz += A.z + B.z;
        dist[2*p] = __float_as_uint(1e10f); dist[2*p+1] = __float_as_uint(1e10f);
    }
    gx *= 0.0625f; gy *= 0.0625f; gz *= 0.0625f;
    float rad = 0.f;
#pragma unroll
    for (int p = 0; p < 8; ++p) {
        float ax, bx, ay, by, az, bz;
        upk2(x2[p], ax, bx); upk2(y2[p], ay, by); upk2(z2[p], az, bz);
        float da = (ax-gx)*(ax-gx) + (ay-gy)*(ay-gy) + (az-gz)*(az-gz);
        float db = (bx-gx)*(bx-gx) + (by-gy)*(by-gy) + (bz-gz)*(bz-gz);
        rad = fmaxf(rad, fmaxf(da, db));
    }
    rad = fmaf(sqrtf(rad), 1.0002f, 1e-6f);    // inflated upper bound
    unsigned gmax = __float_as_uint(1e10f);
    __syncthreads();

    float4 c0 = spts[0];                        // any start point? must be orig idx 0!
    // find orig 0: reference starts at original point 0, not sorted slot 0.
    // Its coords are X[0], X[NPTS], X[2*NPTS] -- read directly.
    float cx = X[0], cy = X[NPTS], cz = X[2*NPTS];
    (void)c0;

    for (int it = 0; it < NS; ++it) {
        if (tid == 0) {
            outxyz[(b*3 + 0)*NS + it] = cx;
            outxyz[(b*3 + 1)*NS + it] = cy;
            outxyz[(b*3 + 2)*NS + it] = cz;
            nxyz[((size_t)b*NS + it)*3 + 0] = cx;
            nxyz[((size_t)b*NS + it)*3 + 1] = cy;
            nxyz[((size_t)b*NS + it)*3 + 2] = cz;
        }
        // conservative prune test (margins >> all fp32 rounding; no false skips)
        float ddx = cx - gx, ddy = cy - gy, ddz = cz - gz;
        float dgc2 = fmaf(ddx, ddx, fmaf(ddy, ddy, ddz * ddz));
        float t = fmaf(sqrtf(dgc2), 0.9999f, -rad);
        bool skip = (t > 0.f) && (t * t * 0.9998f >= __uint_as_float(gmax));

        if (!skip) {
            unsigned long long cx2 = pk2(cx, cx);
            unsigned long long cy2 = pk2(cy, cy);
            unsigned long long cz2 = pk2(cz, cz);
#pragma unroll
            for (int p = 0; p < 8; ++p) {
                unsigned long long dx = f2sub(x2[p], cx2);
                unsigned long long dy = f2sub(y2[p], cy2);
                unsigned long long dz = f2sub(z2[p], cz2);
                unsigned long long s = f2add(f2add(f2mul(dx, dx), f2mul(dy, dy)), f2mul(dz, dz));
                unsigned slo, shi; upk2u(s, slo, shi);
                dist[2*p]   = min(dist[2*p],   slo);
                dist[2*p+1] = min(dist[2*p+1], shi);
            }
            unsigned m = 0u;
#pragma unroll
            for (int j = 0; j < 16; ++j) m = max(m, dist[j]);
            gmax = m;
        }
        unsigned key = gmax;

        unsigned kmax = __reduce_max_sync(0xffffffffu, key);
        if (lane == 0) swm[wid] = kmax;
        __syncthreads();                               // b1
        unsigned g = __reduce_max_sync(0xffffffffu, swm[lane]);  // every warp
        if (tid == 0) swin[(it + 1) & 1] = 0x7fffffff;
        if (key == g) {                                // rare: 1-2 threads
            int cand = 0x7fffffff;
#pragma unroll
            for (int j = 0; j < 16; ++j)
                if (dist[j] == g) cand = min(cand, (oidx[j] << 13) | (tid * 16 + j));
            atomicMin(&swin[it & 1], cand);            // min orig idx -> first occurrence
        }
        __syncthreads();                               // b2
        int wv = swin[it & 1];
        float4 cc = spts[wv & 8191];
        cx = cc.x; cy = cc.y; cz = cc.z;
    }
}

// ---------------- ball query: one warp per center ----------------
__global__ __launch_bounds__(256) void ball_kernel(const float* __restrict__ xyz,
                                                   const float* __restrict__ nxyz,
                                                   int* __restrict__ gidx)
{
    __shared__ int sbuf[8][32];
    int w = threadIdx.x >> 5, lane = threadIdx.x & 31;
    int gid = blockIdx.x * 8 + w;
    int b = gid >> 11, s = gid & 2047;
    const float* X = xyz + (size_t)b * 3 * NPTS;

    float cx = nxyz[gid*3], cy = nxyz[gid*3 + 1], cz = nxyz[gid*3 + 2];
    float cc = __fadd_rn(__fadd_rn(__fmul_rn(cx,cx), __fmul_rn(cy,cy)), __fmul_rn(cz,cz));
    const float R2 = (float)(0.1 * 0.1);

    int cnt = 0;
    for (int base = 0; base < NPTS; base += 32) {
        int n = base + lane;
        float px = X[n], py = X[NPTS + n], pz = X[2*NPTS + n];
        float pp  = __fadd_rn(__fadd_rn(__fmul_rn(px,px), __fmul_rn(py,py)), __fmul_rn(pz,pz));
        float dot = __fadd_rn(__fadd_rn(__fmul_rn(cx,px), __fmul_rn(cy,py)), __fmul_rn(cz,pz));
        float sqr = __fadd_rn(__fadd_rn(cc, pp), -__fmul_rn(2.f, dot));
        bool hit = (sqr <= R2);
        unsigned m = __ballot_sync(0xffffffffu, hit);
        if (m) {
            int rank = cnt + __popc(m & ((1u << lane) - 1u));
            if (hit && rank < 32) sbuf[w][rank] = n;
            cnt += __popc(m);
            if (cnt >= 32) break;
        }
    }
    __syncwarp();
    int first = sbuf[w][0];
    int my = (lane < cnt) ? sbuf[w][lane] : first;
    gidx[((size_t)(b*32 + lane))*2048 + s] = my;
}

// ---------------- gather + center-subtract + concat ----------------
__global__ __launch_bounds__(256) void gather_kernel(const float* __restrict__ xyz,
                                                     const float* __restrict__ pts,
                                                     const int* __restrict__ gidx,
                                                     const float* __restrict__ nxyz,
                                                     float* __restrict__ xin)
{
    int g = blockIdx.x * 256 + threadIdx.x;
    int s = g & 2047, k = (g >> 11) & 31, b = g >> 16;
    int id = gidx[((size_t)(b*32 + k))*2048 + s];
    const float* X = xyz + (size_t)b * 3 * NPTS;
    const float* P = pts + (size_t)b * 29 * NPTS;
    size_t ob = (size_t)b * 32 * MPB + (size_t)k * 2048 + s;
#pragma unroll
    for (int c = 0; c < 3; ++c)
        xin[ob + (size_t)c * MPB] = X[c*NPTS + id] - nxyz[((size_t)(b*2048 + s))*3 + c];
#pragma unroll
    for (int c = 0; c < 29; ++c)
        xin[ob + (size_t)(3 + c) * MPB] = P[c*NPTS + id];
}

// ---------------- conv v3: 256 pts/block, 8 pts/thread, fused stats ----------------
template<int CIN, bool ACT>
__global__ __launch_bounds__(256) void conv_kernel(const float* __restrict__ in,
                                                   const float* __restrict__ W,
                                                   const float* __restrict__ aff,
                                                   float* __restrict__ out,
                                                   float* __restrict__ ps,
                                                   float* __restrict__ pq)
{
    constexpr int CH = CIN / 8;
    __shared__ float sW[CIN][64];
    __shared__ float sX[2][8][256];
    __shared__ float sA[64], sD[64];
    int tid = threadIdx.x, lane = tid & 31, w = tid >> 5;
    int b = blockIdx.x >> 8, mblk = blockIdx.x & 255;
    const float* ip = in + (size_t)b * CIN * MPB + mblk * 256;

    for (int i = tid; i < CIN * 64; i += 256)
        sW[i >> 6][i & 63] = W[(i & 63) * CIN + (i >> 6)];
    if (ACT) for (int i = tid; i < CIN; i += 256) { sA[i] = aff[i]; sD[i] = aff[64 + i]; }

    float4 xa = *(const float4*)(ip + (size_t)w * MPB + lane * 4);
    float4 xb = *(const float4*)(ip + (size_t)w * MPB + 128 + lane * 4);
    float4 na, nb;
    if (CH > 1) {
        na = *(const float4*)(ip + (size_t)(8 + w) * MPB + lane * 4);
        nb = *(const float4*)(ip + (size_t)(8 + w) * MPB + 128 + lane * 4);
    }
    __syncthreads();
    {
        float4 va = xa, vb = xb;
        if (ACT) { float a = sA[w], d = sD[w];
            va.x = fmaxf(fmaf(a, va.x, d), 0.f); va.y = fmaxf(fmaf(a, va.y, d), 0.f);
            va.z = fmaxf(fmaf(a, va.z, d), 0.f); va.w = fmaxf(fmaf(a, va.w, d), 0.f);
            vb.x = fmaxf(fmaf(a, vb.x, d), 0.f); vb.y = fmaxf(fmaf(a, vb.y, d), 0.f);
            vb.z = fmaxf(fmaf(a, vb.z, d), 0.f); vb.w = fmaxf(fmaf(a, vb.w, d), 0.f); }
        *(float4*)&sX[0][w][lane * 4]       = va;
        *(float4*)&sX[0][w][128 + lane * 4] = vb;
    }
    __syncthreads();

    int og = w * 8;
    unsigned long long acc[4][8];
#pragma unroll
    for (int p = 0; p < 4; ++p)
#pragma unroll
        for (int j = 0; j < 8; ++j) acc[p][j] = 0ull;

    for (int k = 0; k < CH; ++k) {
#pragma unroll
        for (int cc = 0; cc < 8; ++cc) {
            int c = k * 8 + cc;
            float4 ua = *(const float4*)&sX[k & 1][cc][lane * 4];
            float4 ub = *(const float4*)&sX[k & 1][cc][128 + lane * 4];
            unsigned long long xp[8] = { pk2(ua.x, ua.x), pk2(ua.y, ua.y),
                                         pk2(ua.z, ua.z), pk2(ua.w, ua.w),
                                         pk2(ub.x, ub.x), pk2(ub.y, ub.y),
                                         pk2(ub.z, ub.z), pk2(ub.w, ub.w) };
            const double2* wp = (const double2*)&sW[c][og];
            double2 w0 = wp[0], w1 = wp[1];
            unsigned long long wq[4] = {
                __double_as_longlong(w0.x), __double_as_longlong(w0.y),
                __double_as_longlong(w1.x), __double_as_longlong(w1.y) };
#pragma unroll
            for (int p = 0; p < 4; ++p)
#pragma unroll
                for (int j = 0; j < 8; ++j)
                    acc[p][j] = f2fma(wq[p], xp[j], acc[p][j]);
        }
        if (k + 1 < CH) {
            float4 va = na, vb = nb;
            if (ACT) { int ch = (k + 1) * 8 + w; float a = sA[ch], d = sD[ch];
                va.x = fmaxf(fmaf(a, va.x, d), 0.f); va.y = fmaxf(fmaf(a, va.y, d), 0.f);
                va.z = fmaxf(fmaf(a, va.z, d), 0.f); va.w = fmaxf(fmaf(a, va.w, d), 0.f);
                vb.x = fmaxf(fmaf(a, vb.x, d), 0.f); vb.y = fmaxf(fmaf(a, vb.y, d), 0.f);
                vb.z = fmaxf(fmaf(a, vb.z, d), 0.f); vb.w = fmaxf(fmaf(a, vb.w, d), 0.f); }
            *(float4*)&sX[(k + 1) & 1][w][lane * 4]       = va;
            *(float4*)&sX[(k + 1) & 1][w][128 + lane * 4] = vb;
            if (k + 2 < CH) {
                na = *(const float4*)(ip + (size_t)((k + 2) * 8 + w) * MPB + lane * 4);
                nb = *(const float4*)(ip + (size_t)((k + 2) * 8 + w) * MPB + 128 + lane * 4);
            }
        }
        __syncthreads();
    }

    float* op = out + (size_t)b * 64 * MPB + mblk * 256;
    int pblk = b * 256 + mblk;
#pragma unroll
    for (int p = 0; p < 4; ++p) {
        float4 a0, a1, b0, b1;
        upk2(acc[p][0], a0.x, a1.x); upk2(acc[p][1], a0.y, a1.y);
        upk2(acc[p][2], a0.z, a1.z); upk2(acc[p][3], a0.w, a1.w);
        upk2(acc[p][4], b0.x, b1.x); upk2(acc[p][5], b0.y, b1.y);
        upk2(acc[p][6], b0.z, b1.z); upk2(acc[p][7], b0.w, b1.w);
        int o0 = og + 2*p, o1 = og + 2*p + 1;
        *(float4*)(op + (size_t)o0 * MPB + lane * 4)       = a0;
        *(float4*)(op + (size_t)o0 * MPB + 128 + lane * 4) = b0;
        *(float4*)(op + (size_t)o1 * MPB + lane * 4)       = a1;
        *(float4*)(op + (size_t)o1 * MPB + 128 + lane * 4) = b1;
        float s0 = (a0.x + a0.y + a0.z + a0.w) + (b0.x + b0.y + b0.z + b0.w);
        float q0 = (a0.x*a0.x + a0.y*a0.y + a0.z*a0.z + a0.w*a0.w)
                 + (b0.x*b0.x + b0.y*b0.y + b0.z*b0.z + b0.w*b0.w);
        float s1 = (a1.x + a1.y + a1.z + a1.w) + (b1.x + b1.y + b1.z + b1.w);
        float q1 = (a1.x*a1.x + a1.y*a1.y + a1.z*a1.z + a1.w*a1.w)
                 + (b1.x*b1.x + b1.y*b1.y + b1.z*b1.z + b1.w*b1.w);
#pragma unroll
        for (int off = 16; off; off >>= 1) {
            s0 += __shfl_xor_sync(0xffffffffu, s0, off);
            q0 += __shfl_xor_sync(0xffffffffu, q0, off);
            s1 += __shfl_xor_sync(0xffffffffu, s1, off);
            q1 += __shfl_xor_sync(0xffffffffu, q1, off);
        }
        if (lane == 0) {
            ps[o0 * NPB + pblk] = s0;  pq[o0 * NPB + pblk] = q0;
            ps[o1 * NPB + pblk] = s1;  pq[o1 * NPB + pblk] = q1;
        }
    }
}

// ---------------- stage-2 stats: NPB partials -> affine coeffs ----------------
__global__ __launch_bounds__(256) void statsfin2_kernel(const float* __restrict__ ps,
                                                        const float* __restrict__ pq,
                                                        const float* __restrict__ gam,
                                                        const float* __restrict__ bet,
                                                        float* __restrict__ aff)
{
    int o = blockIdx.x, tid = threadIdx.x;
    float s = 0.f, q = 0.f;
    for (int i = tid; i < NPB; i += 256) { s += ps[o*NPB + i]; q += pq[o*NPB + i]; }
    __shared__ float rs[256], rq[256];
    rs[tid] = s; rq[tid] = q;
    for (int off = 128; off; off >>= 1) {
        __syncthreads();
        if (tid < off) { rs[tid] += rs[tid + off]; rq[tid] += rq[tid + off]; }
    }
    if (tid == 0) {
        const float invn = 1.f / (float)(NB * MPB);
        float mean = rs[0] * invn;
        float var  = rq[0] * invn - mean * mean;
        float a = gam[o] * rsqrtf(var + 1e-5f);
        aff[o] = a;
        aff[64 + o] = bet[o] - a * mean;
    }
}

// ---------------- residual: x1 = relu(aff2(t2) + relu(aff0(y0))) ----------------
__global__ __launch_bounds__(256) void resid_kernel(const float* __restrict__ y0,
                                                    const float* __restrict__ t2,
                                                    const float* __restrict__ aff0,
                                                    const float* __restrict__ aff2,
                                                    float* __restrict__ x1)
{
    size_t i = (size_t)blockIdx.x * 256 + threadIdx.x;
    int c = (int)((i >> 14) & 63);
    float a0 = aff0[c], d0 = aff0[64+c], a2 = aff2[c], d2 = aff2[64+c];
    float4 y = ((const float4*)y0)[i];
    float4 t = ((const float4*)t2)[i];
    float4 r;
    r.x = fmaxf(fmaf(a2, t.x, d2) + fmaxf(fmaf(a0, y.x, d0), 0.f), 0.f);
    r.y = fmaxf(fmaf(a2, t.y, d2) + fmaxf(fmaf(a0, y.y, d0), 0.f), 0.f);
    r.z = fmaxf(fmaf(a2, t.z, d2) + fmaxf(fmaf(a0, y.z, d0), 0.f), 0.f);
    r.w = fmaxf(fmaf(a2, t.w, d2) + fmaxf(fmaf(a0, y.w, d0), 0.f), 0.f);
    ((float4*)x1)[i] = r;
}

// ---------------- final: feat = max_k relu(aff4(t4) + x1) ----------------
__global__ __launch_bounds__(256) void finalmax_kernel(const float* __restrict__ t4,
                                                       const float* __restrict__ x1,
                                                       const float* __restrict__ aff,
                                                       float* __restrict__ outf)
{
    int g = blockIdx.x * 256 + threadIdx.x;
    int s = g & 2047, o = (g >> 11) & 63, b = g >> 17;
    float a = aff[o], d = aff[64 + o];
    size_t base = (size_t)(b*64 + o) * MPB + s;
    const float* tp = t4 + base;
    const float* xp = x1 + base;
    float m = -1e30f;
#pragma unroll 8
    for (int k = 0; k < 32; ++k)
        m = fmaxf(m, fmaf(a, tp[(size_t)k*2048], d) + xp[(size_t)k*2048]);
    outf[g] = fmaxf(m, 0.f);
}

extern "C" void kernel_launch(void* const* d_in, const int* in_sizes, int n_in,
                              void* d_out, int out_size)
{
    (void)in_sizes; (void)n_in; (void)out_size;
    const float* xyz = (const float*)d_in[0];
    const float* pts = (const float*)d_in[1];
    const float* pw  = (const float*)d_in[2];
    const float* pg  = (const float*)d_in[3];
    const float* pb  = (const float*)d_in[4];
    const float* w1  = (const float*)d_in[5];
    const float* g1  = (const float*)d_in[6];
    const float* b1  = (const float*)d_in[7];
    const float* w2  = (const float*)d_in[8];
    const float* g2  = (const float*)d_in[9];
    const float* b2  = (const float*)d_in[10];

    float *y0, *t1, *t2, *x1, *nx, *ps, *pq, *aff; int* gi;
    cudaGetSymbolAddress((void**)&y0,  g_y0);
    cudaGetSymbolAddress((void**)&t1,  g_t1);
    cudaGetSymbolAddress((void**)&t2,  g_t2);
    cudaGetSymbolAddress((void**)&x1,  g_x1);
    cudaGetSymbolAddress((void**)&nx,  g_nxyz);
    cudaGetSymbolAddress((void**)&gi,  g_idx);
    cudaGetSymbolAddress((void**)&ps,  g_ps);
    cudaGetSymbolAddress((void**)&pq,  g_pq);
    cudaGetSymbolAddress((void**)&aff, g_aff);
    float* out = (float*)d_out;

    cudaFuncSetAttribute(fps_kernel, cudaFuncAttributeMaxDynamicSharedMemorySize,
                         NPTS * (int)sizeof(float4));

    fps_kernel<<<NB, 512, NPTS * sizeof(float4)>>>(xyz, out, nx);
    ball_kernel<<<1024, 256>>>(xyz, nx, gi);
    gather_kernel<<<1024, 256>>>(xyz, pts, gi, nx, t2);

    conv_kernel<32, false><<<1024, 256>>>(t2, pw, nullptr, y0, ps, pq);
    statsfin2_kernel<<<64, 256>>>(ps, pq, pg, pb, aff);

    conv_kernel<64, true><<<1024, 256>>>(y0, w1, aff, t1, ps, pq);
    statsfin2_kernel<<<64, 256>>>(ps, pq, g1, b1, aff + 128);

    conv_kernel<64, true><<<1024, 256>>>(t1, w2, aff + 128, t2, ps, pq);
    statsfin2_kernel<<<64, 256>>>(ps, pq, g2, b2, aff + 256);

    resid_kernel<<<16384, 256>>>(y0, t2, aff, aff + 256, x1);

    conv_kernel<64, false><<<1024, 256>>>(x1, w1 + 4096, nullptr, t1, ps, pq);
    statsfin2_kernel<<<64, 256>>>(ps, pq, g1 + 64, b1 + 64, aff + 384);

    conv_kernel<64, true><<<1024, 256>>>(t1, w2 + 4096, aff + 384, t2, ps, pq);
    statsfin2_kernel<<<64, 256>>>(ps, pq, g2 + 64, b2 + 64, aff + 512);

    finalmax_kernel<<<2048, 256>>>(t2, x1, aff + 512, out + NB*3*NS);
}

// round 10
// speedup vs baseline: 1.0494x; 1.0494x over previous
#include <cuda_runtime.h>
#include <cstdint>

#define NPTS 8192
#define NS   2048
#define NK   32
#define NB   4
#define MPB  65536              /* NK*NS per batch */
#define FSZ  (NB*64*MPB)        /* 16.7M floats per feature buffer */
#define NPB  1024               /* stats partial blocks (4*256) */

__device__ float g_y0[FSZ];
__device__ float g_t1[FSZ];
__device__ float g_t2[FSZ];
__device__ float g_x1[FSZ];
__device__ float g_nxyz[NB*NS*3];
__device__ int   g_idx[NB*NK*NS];
__device__ float g_ps[64*2048];
__device__ float g_pq[64*2048];
__device__ float g_aff[5*128];

static __device__ __forceinline__ unsigned long long pk2(float lo, float hi){
    unsigned long long r; asm("mov.b64 %0,{%1,%2};" : "=l"(r) : "f"(lo), "f"(hi)); return r;
}
static __device__ __forceinline__ void upk2(unsigned long long v, float& lo, float& hi){
    asm("mov.b64 {%0,%1},%2;" : "=f"(lo), "=f"(hi) : "l"(v));
}
static __device__ __forceinline__ void upk2u(unsigned long long v, unsigned& lo, unsigned& hi){
    asm("mov.b64 {%0,%1},%2;" : "=r"(lo), "=r"(hi) : "l"(v));
}
static __device__ __forceinline__ unsigned long long f2fma(unsigned long long a, unsigned long long b, unsigned long long c){
    unsigned long long r; asm("fma.rn.f32x2 %0,%1,%2,%3;" : "=l"(r) : "l"(a), "l"(b), "l"(c)); return r;
}
static __device__ __forceinline__ unsigned long long f2mul(unsigned long long a, unsigned long long b){
    unsigned long long r; asm("mul.rn.f32x2 %0,%1,%2;" : "=l"(r) : "l"(a), "l"(b)); return r;
}
static __device__ __forceinline__ unsigned long long f2add(unsigned long long a, unsigned long long b){
    unsigned long long r; asm("add.rn.f32x2 %0,%1,%2;" : "=l"(r) : "l"(a), "l"(b)); return r;
}
static __device__ __forceinline__ unsigned long long f2sub(unsigned long long a, unsigned long long b){
    unsigned long long r; asm("sub.rn.f32x2 %0,%1,%2;" : "=l"(r) : "l"(a), "l"(b)); return r;
}
static __device__ __forceinline__ int mort3(int v){   // spread 3 bits
    return (v & 1) | ((v & 2) << 1) | ((v & 4) << 2);
}

// ---------------- FPS v5: Morton sort + warp-voted exact-safe pruning ----------------
// Points counting-sorted into 8x8x8 cells in MORTON order so a warp's 512
// consecutive points form a compact block. Per iteration each thread tests a
// conservative bound; the warp skips the exact distance chain only when ALL
// lanes can prove their min-updates are no-ops -> outputs bit-identical.
extern __shared__ float4 spts[];    // 8192 sorted points, .w = orig index bits

__global__ __launch_bounds__(512, 1) void fps_kernel(const float* __restrict__ xyz,
                                                     float* __restrict__ outxyz,
                                                     float* __restrict__ nxyz)
{
    int b = blockIdx.x, tid = threadIdx.x;
    int lane = tid & 31, wid = tid >> 5;     // 16 warps
    const float* X = xyz + (size_t)b * 3 * NPTS;

    __shared__ unsigned swm[32];
    __shared__ int swin[2];
    __shared__ int hist[512];
    __shared__ int wsum[16];

    hist[tid] = 0;
    if (tid < 2) swin[tid] = 0x7fffffff;
    if (tid >= 16 && tid < 32) swm[tid] = 0u;
    __syncthreads();

    // pass 1: cell counts (Morton index)
#pragma unroll 4
    for (int j = 0; j < 16; ++j) {
        int n = tid + j * 512;
        float x = X[n], y = X[NPTS + n], z = X[2*NPTS + n];
        int ix = min(7, (int)(x * 8.f)), iy = min(7, (int)(y * 8.f)), iz = min(7, (int)(z * 8.f));
        int cell = mort3(ix) | (mort3(iy) << 1) | (mort3(iz) << 2);
        atomicAdd(&hist[cell], 1);
    }
    __syncthreads();

    // exclusive scan of hist[512]
    int v = hist[tid];
    int inc = v;
#pragma unroll
    for (int off = 1; off < 32; off <<= 1) {
        int o = __shfl_up_sync(0xffffffffu, inc, off);
        if (lane >= off) inc += o;
    }
    if (lane == 31) wsum[wid] = inc;
    __syncthreads();
    if (wid == 0) {
        int s = (lane < 16) ? wsum[lane] : 0;
#pragma unroll
        for (int off = 1; off < 16; off <<= 1) {
            int o = __shfl_up_sync(0xffffffffu, s, off);
            if (lane >= off) s += o;
        }
        if (lane < 16) wsum[lane] = s;
    }
    __syncthreads();
    int wbase = (wid > 0) ? wsum[wid - 1] : 0;
    hist[tid] = wbase + inc - v;               // exclusive start, becomes running
    __syncthreads();

    // pass 2: scatter into sorted smem mirror
#pragma unroll 4
    for (int j = 0; j < 16; ++j) {
        int n = tid + j * 512;
        float x = X[n], y = X[NPTS + n], z = X[2*NPTS + n];
        int ix = min(7, (int)(x * 8.f)), iy = min(7, (int)(y * 8.f)), iz = min(7, (int)(z * 8.f));
        int cell = mort3(ix) | (mort3(iy) << 1) | (mort3(iz) << 2);
        int pos = atomicAdd(&hist[cell], 1);
        spts[pos] = make_float4(x, y, z, __int_as_float(n));
    }
    __syncthreads();

    // load my 16 sorted points; centroid + conservative radius
    unsigned long long x2[8], y2[8], z2[8];
    unsigned dist[16];
    int oidx[16];
    float gx = 0.f, gy = 0.f, gz = 0.f;
#pragma unroll
    for (int p = 0; p < 8; ++p) {
        float4 A = spts[tid * 16 + 2*p];
        float4 B = spts[tid * 16 + 2*p + 1];
        x2[p] = pk2(A.x, B.x); y2[p] = pk2(A.y, B.y); z2[p] = pk2(A.z, B.z);
        oidx[2*p] = __float_as_int(A.w); oidx[2*p+1] = __float_as_int(B.w);
        gx += A.x + B.x; gy += A.y + B.y; gz += A.z + B.z;
        dist[2*p] = __float_as_uint(1e10f); dist[2*p+1] = __float_as_uint(1e10f);
    }
    gx *= 0.0625f; gy *= 0.0625f; gz *= 0.0625f;
    float rad = 0.f;
#pragma unroll
    for (int p = 0; p < 8; ++p) {
        float ax, bx, ay, by, az, bz;
        upk2(x2[p], ax, bx); upk2(y2[p], ay, by); upk2(z2[p], az, bz);
        float da = (ax-gx)*(ax-gx) + (ay-gy)*(ay-gy) + (az-gz)*(az-gz);
        float db = (bx-gx)*(bx-gx) + (by-gy)*(by-gy) + (bz-gz)*(bz-gz);
        rad = fmaxf(rad, fmaxf(da, db));
    }
    rad = fmaf(sqrtf(rad), 1.0002f, 1e-6f);    // inflated upper bound
    unsigned gmax = __float_as_uint(1e10f);
    float Rr = rad + sqrtf(1e10f) * 1.0002f;   // cached rad + sqrt(gmax), inflated
    float Rsq = Rr * Rr;
    __syncthreads();

    float cx = X[0], cy = X[NPTS], cz = X[2*NPTS];   // start = original point 0

    for (int it = 0; it < NS; ++it) {
        if (tid == 0) {
            outxyz[(b*3 + 0)*NS + it] = cx;
            outxyz[(b*3 + 1)*NS + it] = cy;
            outxyz[(b*3 + 2)*NS + it] = cz;
            nxyz[((size_t)b*NS + it)*3 + 0] = cx;
            nxyz[((size_t)b*NS + it)*3 + 1] = cy;
            nxyz[((size_t)b*NS + it)*3 + 2] = cz;
        }
        // conservative no-op test (margins >> fp32 rounding; no false skips)
        float ddx = cx - gx, ddy = cy - gy, ddz = cz - gz;
        float dgc2 = fmaf(ddx, ddx, fmaf(ddy, ddy, ddz * ddz));
        bool myskip = (dgc2 * 0.9997f > Rsq);
        bool wskip = __all_sync(0xffffffffu, myskip);   // whole-warp skip only

        if (!wskip) {
            unsigned long long cx2 = pk2(cx, cx);
            unsigned long long cy2 = pk2(cy, cy);
            unsigned long long cz2 = pk2(cz, cz);
#pragma unroll
            for (int p = 0; p < 8; ++p) {
                unsigned long long dx = f2sub(x2[p], cx2);
                unsigned long long dy = f2sub(y2[p], cy2);
                unsigned long long dz = f2sub(z2[p], cz2);
                unsigned long long s = f2add(f2add(f2mul(dx, dx), f2mul(dy, dy)), f2mul(dz, dz));
                unsigned slo, shi; upk2u(s, slo, shi);
                dist[2*p]   = min(dist[2*p],   slo);
                dist[2*p+1] = min(dist[2*p+1], shi);
            }
            unsigned m = 0u;
#pragma unroll
            for (int j = 0; j < 16; ++j) m = max(m, dist[j]);
            gmax = m;
            Rr = fmaf(sqrtf(__uint_as_float(gmax)), 1.0002f, rad);
            Rsq = Rr * Rr;
        }
        unsigned key = gmax;

        unsigned kmax = __reduce_max_sync(0xffffffffu, key);
        if (lane == 0) swm[wid] = kmax;
        __syncthreads();                               // b1
        unsigned g = __reduce_max_sync(0xffffffffu, swm[lane]);  // every warp
        if (tid == 0) swin[(it + 1) & 1] = 0x7fffffff;
        if (key == g) {                                // rare: 1-2 threads
            int cand = 0x7fffffff;
#pragma unroll
            for (int j = 0; j < 16; ++j)
                if (dist[j] == g) cand = min(cand, (oidx[j] << 13) | (tid * 16 + j));
            atomicMin(&swin[it & 1], cand);            // min orig idx -> first occurrence
        }
        __syncthreads();                               // b2
        int wv = swin[it & 1];
        float4 cc = spts[wv & 8191];
        cx = cc.x; cy = cc.y; cz = cc.z;
    }
}

// ---------------- ball query: one warp per center ----------------
__global__ __launch_bounds__(256) void ball_kernel(const float* __restrict__ xyz,
                                                   const float* __restrict__ nxyz,
                                                   int* __restrict__ gidx)
{
    __shared__ int sbuf[8][32];
    int w = threadIdx.x >> 5, lane = threadIdx.x & 31;
    int gid = blockIdx.x * 8 + w;
    int b = gid >> 11, s = gid & 2047;
    const float* X = xyz + (size_t)b * 3 * NPTS;

    float cx = nxyz[gid*3], cy = nxyz[gid*3 + 1], cz = nxyz[gid*3 + 2];
    float cc = __fadd_rn(__fadd_rn(__fmul_rn(cx,cx), __fmul_rn(cy,cy)), __fmul_rn(cz,cz));
    const float R2 = (float)(0.1 * 0.1);

    int cnt = 0;
    for (int base = 0; base < NPTS; base += 32) {
        int n = base + lane;
        float px = X[n], py = X[NPTS + n], pz = X[2*NPTS + n];
        float pp  = __fadd_rn(__fadd_rn(__fmul_rn(px,px), __fmul_rn(py,py)), __fmul_rn(pz,pz));
        float dot = __fadd_rn(__fadd_rn(__fmul_rn(cx,px), __fmul_rn(cy,py)), __fmul_rn(cz,pz));
        float sqr = __fadd_rn(__fadd_rn(cc, pp), -__fmul_rn(2.f, dot));
        bool hit = (sqr <= R2);
        unsigned m = __ballot_sync(0xffffffffu, hit);
        if (m) {
            int rank = cnt + __popc(m & ((1u << lane) - 1u));
            if (hit && rank < 32) sbuf[w][rank] = n;
            cnt += __popc(m);
            if (cnt >= 32) break;
        }
    }
    __syncwarp();
    int first = sbuf[w][0];
    int my = (lane < cnt) ? sbuf[w][lane] : first;
    gidx[((size_t)(b*32 + lane))*2048 + s] = my;
}

// ---------------- gather + center-subtract + concat ----------------
__global__ __launch_bounds__(256) void gather_kernel(const float* __restrict__ xyz,
                                                     const float* __restrict__ pts,
                                                     const int* __restrict__ gidx,
                                                     const float* __restrict__ nxyz,
                                                     float* __restrict__ xin)
{
    int g = blockIdx.x * 256 + threadIdx.x;
    int s = g & 2047, k = (g >> 11) & 31, b = g >> 16;
    int id = gidx[((size_t)(b*32 + k))*2048 + s];
    const float* X = xyz + (size_t)b * 3 * NPTS;
    const float* P = pts + (size_t)b * 29 * NPTS;
    size_t ob = (size_t)b * 32 * MPB + (size_t)k * 2048 + s;
#pragma unroll
    for (int c = 0; c < 3; ++c)
        xin[ob + (size_t)c * MPB] = X[c*NPTS + id] - nxyz[((size_t)(b*2048 + s))*3 + c];
#pragma unroll
    for (int c = 0; c < 29; ++c)
        xin[ob + (size_t)(3 + c) * MPB] = P[c*NPTS + id];
}

// ---------------- conv v3: 256 pts/block, 8 pts/thread, fused stats ----------------
template<int CIN, bool ACT>
__global__ __launch_bounds__(256) void conv_kernel(const float* __restrict__ in,
                                                   const float* __restrict__ W,
                                                   const float* __restrict__ aff,
                                                   float* __restrict__ out,
                                                   float* __restrict__ ps,
                                                   float* __restrict__ pq)
{
    constexpr int CH = CIN / 8;
    __shared__ float sW[CIN][64];
    __shared__ float sX[2][8][256];
    __shared__ float sA[64], sD[64];
    int tid = threadIdx.x, lane = tid & 31, w = tid >> 5;
    int b = blockIdx.x >> 8, mblk = blockIdx.x & 255;
    const float* ip = in + (size_t)b * CIN * MPB + mblk * 256;

    for (int i = tid; i < CIN * 64; i += 256)
        sW[i >> 6][i & 63] = W[(i & 63) * CIN + (i >> 6)];
    if (ACT) for (int i = tid; i < CIN; i += 256) { sA[i] = aff[i]; sD[i] = aff[64 + i]; }

    float4 xa = *(const float4*)(ip + (size_t)w * MPB + lane * 4);
    float4 xb = *(const float4*)(ip + (size_t)w * MPB + 128 + lane * 4);
    float4 na, nb;
    if (CH > 1) {
        na = *(const float4*)(ip + (size_t)(8 + w) * MPB + lane * 4);
        nb = *(const float4*)(ip + (size_t)(8 + w) * MPB + 128 + lane * 4);
    }
    __syncthreads();
    {
        float4 va = xa, vb = xb;
        if (ACT) { float a = sA[w], d = sD[w];
            va.x = fmaxf(fmaf(a, va.x, d), 0.f); va.y = fmaxf(fmaf(a, va.y, d), 0.f);
            va.z = fmaxf(fmaf(a, va.z, d), 0.f); va.w = fmaxf(fmaf(a, va.w, d), 0.f);
            vb.x = fmaxf(fmaf(a, vb.x, d), 0.f); vb.y = fmaxf(fmaf(a, vb.y, d), 0.f);
            vb.z = fmaxf(fmaf(a, vb.z, d), 0.f); vb.w = fmaxf(fmaf(a, vb.w, d), 0.f); }
        *(float4*)&sX[0][w][lane * 4]       = va;
        *(float4*)&sX[0][w][128 + lane * 4] = vb;
    }
    __syncthreads();

    int og = w * 8;
    unsigned long long acc[4][8];
#pragma unroll
    for (int p = 0; p < 4; ++p)
#pragma unroll
        for (int j = 0; j < 8; ++j) acc[p][j] = 0ull;

    for (int k = 0; k < CH; ++k) {
#pragma unroll
        for (int cc = 0; cc < 8; ++cc) {
            int c = k * 8 + cc;
            float4 ua = *(const float4*)&sX[k & 1][cc][lane * 4];
            float4 ub = *(const float4*)&sX[k & 1][cc][128 + lane * 4];
            unsigned long long xp[8] = { pk2(ua.x, ua.x), pk2(ua.y, ua.y),
                                         pk2(ua.z, ua.z), pk2(ua.w, ua.w),
                                         pk2(ub.x, ub.x), pk2(ub.y, ub.y),
                                         pk2(ub.z, ub.z), pk2(ub.w, ub.w) };
            const double2* wp = (const double2*)&sW[c][og];
            double2 w0 = wp[0], w1 = wp[1];
            unsigned long long wq[4] = {
                __double_as_longlong(w0.x), __double_as_longlong(w0.y),
                __double_as_longlong(w1.x), __double_as_longlong(w1.y) };
#pragma unroll
            for (int p = 0; p < 4; ++p)
#pragma unroll
                for (int j = 0; j < 8; ++j)
                    acc[p][j] = f2fma(wq[p], xp[j], acc[p][j]);
        }
        if (k + 1 < CH) {
            float4 va = na, vb = nb;
            if (ACT) { int ch = (k + 1) * 8 + w; float a = sA[ch], d = sD[ch];
                va.x = fmaxf(fmaf(a, va.x, d), 0.f); va.y = fmaxf(fmaf(a, va.y, d), 0.f);
                va.z = fmaxf(fmaf(a, va.z, d), 0.f); va.w = fmaxf(fmaf(a, va.w, d), 0.f);
                vb.x = fmaxf(fmaf(a, vb.x, d), 0.f); vb.y = fmaxf(fmaf(a, vb.y, d), 0.f);
                vb.z = fmaxf(fmaf(a, vb.z, d), 0.f); vb.w = fmaxf(fmaf(a, vb.w, d), 0.f); }
            *(float4*)&sX[(k + 1) & 1][w][lane * 4]       = va;
            *(float4*)&sX[(k + 1) & 1][w][128 + lane * 4] = vb;
            if (k + 2 < CH) {
                na = *(const float4*)(ip + (size_t)((k + 2) * 8 + w) * MPB + lane * 4);
                nb = *(const float4*)(ip + (size_t)((k + 2) * 8 + w) * MPB + 128 + lane * 4);
            }
        }
        __syncthreads();
    }

    float* op = out + (size_t)b * 64 * MPB + mblk * 256;
    int pblk = b * 256 + mblk;
#pragma unroll
    for (int p = 0; p < 4; ++p) {
        float4 a0, a1, b0, b1;
        upk2(acc[p][0], a0.x, a1.x); upk2(acc[p][1], a0.y, a1.y);
        upk2(acc[p][2], a0.z, a1.z); upk2(acc[p][3], a0.w, a1.w);
        upk2(acc[p][4], b0.x, b1.x); upk2(acc[p][5], b0.y, b1.y);
        upk2(acc[p][6], b0.z, b1.z); upk2(acc[p][7], b0.w, b1.w);
        int o0 = og + 2*p, o1 = og + 2*p + 1;
        *(float4*)(op + (size_t)o0 * MPB + lane * 4)       = a0;
        *(float4*)(op + (size_t)o0 * MPB + 128 + lane * 4) = b0;
        *(float4*)(op + (size_t)o1 * MPB + lane * 4)       = a1;
        *(float4*)(op + (size_t)o1 * MPB + 128 + lane * 4) = b1;
        float s0 = (a0.x + a0.y + a0.z + a0.w) + (b0.x + b0.y + b0.z + b0.w);
        float q0 = (a0.x*a0.x + a0.y*a0.y + a0.z*a0.z + a0.w*a0.w)
                 + (b0.x*b0.x + b0.y*b0.y + b0.z*b0.z + b0.w*b0.w);
        float s1 = (a1.x + a1.y + a1.z + a1.w) + (b1.x + b1.y + b1.z + b1.w);
        float q1 = (a1.x*a1.x + a1.y*a1.y + a1.z*a1.z + a1.w*a1.w)
                 + (b1.x*b1.x + b1.y*b1.y + b1.z*b1.z + b1.w*b1.w);
#pragma unroll
        for (int off = 16; off; off >>= 1) {
            s0 += __shfl_xor_sync(0xffffffffu, s0, off);
            q0 += __shfl_xor_sync(0xffffffffu, q0, off);
            s1 += __shfl_xor_sync(0xffffffffu, s1, off);
            q1 += __shfl_xor_sync(0xffffffffu, q1, off);
        }
        if (lane == 0) {
            ps[o0 * NPB + pblk] = s0;  pq[o0 * NPB + pblk] = q0;
            ps[o1 * NPB + pblk] = s1;  pq[o1 * NPB + pblk] = q1;
        }
    }
}

// ---------------- stage-2 stats: NPB partials -> affine coeffs ----------------
__global__ __launch_bounds__(256) void statsfin2_kernel(const float* __restrict__ ps,
                                                        const float* __restrict__ pq,
                                                        const float* __restrict__ gam,
                                                        const float* __restrict__ bet,
                                                        float* __restrict__ aff)
{
    int o = blockIdx.x, tid = threadIdx.x;
    float s = 0.f, q = 0.f;
    for (int i = tid; i < NPB; i += 256) { s += ps[o*NPB + i]; q += pq[o*NPB + i]; }
    __shared__ float rs[256], rq[256];
    rs[tid] = s; rq[tid] = q;
    for (int off = 128; off; off >>= 1) {
        __syncthreads();
        if (tid < off) { rs[tid] += rs[tid + off]; rq[tid] += rq[tid + off]; }
    }
    if (tid == 0) {
        const float invn = 1.f / (float)(NB * MPB);
        float mean = rs[0] * invn;
        float var  = rq[0] * invn - mean * mean;
        float a = gam[o] * rsqrtf(var + 1e-5f);
        aff[o] = a;
        aff[64 + o] = bet[o] - a * mean;
    }
}

// ---------------- residual: x1 = relu(aff2(t2) + relu(aff0(y0))) ----------------
__global__ __launch_bounds__(256) void resid_kernel(const float* __restrict__ y0,
                                                    const float* __restrict__ t2,
                                                    const float* __restrict__ aff0,
                                                    const float* __restrict__ aff2,
                                                    float* __restrict__ x1)
{
    size_t i = (size_t)blockIdx.x * 256 + threadIdx.x;
    int c = (int)((i >> 14) & 63);
    float a0 = aff0[c], d0 = aff0[64+c], a2 = aff2[c], d2 = aff2[64+c];
    float4 y = ((const float4*)y0)[i];
    float4 t = ((const float4*)t2)[i];
    float4 r;
    r.x = fmaxf(fmaf(a2, t.x, d2) + fmaxf(fmaf(a0, y.x, d0), 0.f), 0.f);
    r.y = fmaxf(fmaf(a2, t.y, d2) + fmaxf(fmaf(a0, y.y, d0), 0.f), 0.f);
    r.z = fmaxf(fmaf(a2, t.z, d2) + fmaxf(fmaf(a0, y.z, d0), 0.f), 0.f);
    r.w = fmaxf(fmaf(a2, t.w, d2) + fmaxf(fmaf(a0, y.w, d0), 0.f), 0.f);
    ((float4*)x1)[i] = r;
}

// ---------------- final: feat = max_k relu(aff4(t4) + x1) ----------------
__global__ __launch_bounds__(256) void finalmax_kernel(const float* __restrict__ t4,
                                                       const float* __restrict__ x1,
                                                       const float* __restrict__ aff,
                                                       float* __restrict__ outf)
{
    int g = blockIdx.x * 256 + threadIdx.x;
    int s = g & 2047, o = (g >> 11) & 63, b = g >> 17;
    float a = aff[o], d = aff[64 + o];
    size_t base = (size_t)(b*64 + o) * MPB + s;
    const float* tp = t4 + base;
    const float* xp = x1 + base;
    float m = -1e30f;
#pragma unroll 8
    for (int k = 0; k < 32; ++k)
        m = fmaxf(m, fmaf(a, tp[(size_t)k*2048], d) + xp[(size_t)k*2048]);
    outf[g] = fmaxf(m, 0.f);
}

extern "C" void kernel_launch(void* const* d_in, const int* in_sizes, int n_in,
                              void* d_out, int out_size)
{
    (void)in_sizes; (void)n_in; (void)out_size;
    const float* xyz = (const float*)d_in[0];
    const float* pts = (const float*)d_in[1];
    const float* pw  = (const float*)d_in[2];
    const float* pg  = (const float*)d_in[3];
    const float* pb  = (const float*)d_in[4];
    const float* w1  = (const float*)d_in[5];
    const float* g1  = (const float*)d_in[6];
    const float* b1  = (const float*)d_in[7];
    const float* w2  = (const float*)d_in[8];
    const float* g2  = (const float*)d_in[9];
    const float* b2  = (const float*)d_in[10];

    float *y0, *t1, *t2, *x1, *nx, *ps, *pq, *aff; int* gi;
    cudaGetSymbolAddress((void**)&y0,  g_y0);
    cudaGetSymbolAddress((void**)&t1,  g_t1);
    cudaGetSymbolAddress((void**)&t2,  g_t2);
    cudaGetSymbolAddress((void**)&x1,  g_x1);
    cudaGetSymbolAddress((void**)&nx,  g_nxyz);
    cudaGetSymbolAddress((void**)&gi,  g_idx);
    cudaGetSymbolAddress((void**)&ps,  g_ps);
    cudaGetSymbolAddress((void**)&pq,  g_pq);
    cudaGetSymbolAddress((void**)&aff, g_aff);
    float* out = (float*)d_out;

    cudaFuncSetAttribute(fps_kernel, cudaFuncAttributeMaxDynamicSharedMemorySize,
                         NPTS * (int)sizeof(float4));

    fps_kernel<<<NB, 512, NPTS * sizeof(float4)>>>(xyz, out, nx);
    ball_kernel<<<1024, 256>>>(xyz, nx, gi);
    gather_kernel<<<1024, 256>>>(xyz, pts, gi, nx, t2);

    conv_kernel<32, false><<<1024, 256>>>(t2, pw, nullptr, y0, ps, pq);
    statsfin2_kernel<<<64, 256>>>(ps, pq, pg, pb, aff);

    conv_kernel<64, true><<<1024, 256>>>(y0, w1, aff, t1, ps, pq);
    statsfin2_kernel<<<64, 256>>>(ps, pq, g1, b1, aff + 128);

    conv_kernel<64, true><<<1024, 256>>>(t1, w2, aff + 128, t2, ps, pq);
    statsfin2_kernel<<<64, 256>>>(ps, pq, g2, b2, aff + 256);

    resid_kernel<<<16384, 256>>>(y0, t2, aff, aff + 256, x1);

    conv_kernel<64, false><<<1024, 256>>>(x1, w1 + 4096, nullptr, t1, ps, pq);
    statsfin2_kernel<<<64, 256>>>(ps, pq, g1 + 64, b1 + 64, aff + 384);

    conv_kernel<64, true><<<1024, 256>>>(t1, w2 + 4096, aff + 384, t2, ps, pq);
    statsfin2_kernel<<<64, 256>>>(ps, pq, g2 + 64, b2 + 64, aff + 512);

    finalmax_kernel<<<2048, 256>>>(t2, x1, aff + 512, out + NB*3*NS);
}

// round 11
// speedup vs baseline: 1.0613x; 1.0113x over previous
#include <cuda_runtime.h>
#include <cstdint>

#define NPTS 8192
#define NS   2048
#define NK   32
#define NB   4
#define MPB  65536              /* NK*NS per batch */
#define FSZ  (NB*64*MPB)        /* 16.7M floats per feature buffer */
#define NPB  1024               /* stats partial blocks (4*256) */

__device__ float g_y0[FSZ];
__device__ float g_t1[FSZ];
__device__ float g_t2[FSZ];
__device__ float g_x1[FSZ];
__device__ float g_nxyz[NB*NS*3];
__device__ int   g_idx[NB*NK*NS];
__device__ float g_ps[64*2048];
__device__ float g_pq[64*2048];
__device__ float g_aff[5*128];

static __device__ __forceinline__ unsigned long long pk2(float lo, float hi){
    unsigned long long r; asm("mov.b64 %0,{%1,%2};" : "=l"(r) : "f"(lo), "f"(hi)); return r;
}
static __device__ __forceinline__ void upk2(unsigned long long v, float& lo, float& hi){
    asm("mov.b64 {%0,%1},%2;" : "=f"(lo), "=f"(hi) : "l"(v));
}
static __device__ __forceinline__ void upk2u(unsigned long long v, unsigned& lo, unsigned& hi){
    asm("mov.b64 {%0,%1},%2;" : "=r"(lo), "=r"(hi) : "l"(v));
}
static __device__ __forceinline__ unsigned long long f2fma(unsigned long long a, unsigned long long b, unsigned long long c){
    unsigned long long r; asm("fma.rn.f32x2 %0,%1,%2,%3;" : "=l"(r) : "l"(a), "l"(b), "l"(c)); return r;
}
static __device__ __forceinline__ unsigned long long f2mul(unsigned long long a, unsigned long long b){
    unsigned long long r; asm("mul.rn.f32x2 %0,%1,%2;" : "=l"(r) : "l"(a), "l"(b)); return r;
}
static __device__ __forceinline__ unsigned long long f2add(unsigned long long a, unsigned long long b){
    unsigned long long r; asm("add.rn.f32x2 %0,%1,%2;" : "=l"(r) : "l"(a), "l"(b)); return r;
}
static __device__ __forceinline__ unsigned long long f2sub(unsigned long long a, unsigned long long b){
    unsigned long long r; asm("sub.rn.f32x2 %0,%1,%2;" : "=l"(r) : "l"(a), "l"(b)); return r;
}

// ---------------- FPS v6: one block/batch, 256 threads x 32 points ----------------
// Exact-rounding sub/mul/add distance chain (trajectory bit-identical to the
// R7 baseline); min/max as uint on the ALU pipe (monotonic for nonneg floats);
// deferred first-occurrence argmax; 2 barriers/iteration; 8-warp tail.
extern __shared__ float4 spts[];

__global__ __launch_bounds__(256, 1) void fps_kernel(const float* __restrict__ xyz,
                                                     float* __restrict__ outxyz,
                                                     float* __restrict__ nxyz)
{
    int b = blockIdx.x, tid = threadIdx.x;
    int lane = tid & 31, wid = tid >> 5;     // 8 warps
    const float* X = xyz + (size_t)b * 3 * NPTS;

    __shared__ unsigned swm[32];
    __shared__ int swin[2];

    unsigned long long x2[16], y2[16], z2[16];
    unsigned dist[32];
#pragma unroll
    for (int p = 0; p < 16; ++p) {
        int na = tid + (2*p)   * 256;
        int nb = tid + (2*p+1) * 256;
        float xa = X[na],        xbv = X[nb];
        float ya = X[NPTS+na],   yb  = X[NPTS+nb];
        float za = X[2*NPTS+na], zb  = X[2*NPTS+nb];
        x2[p] = pk2(xa, xbv); y2[p] = pk2(ya, yb); z2[p] = pk2(za, zb);
        spts[na] = make_float4(xa, ya, za, 0.f);
        spts[nb] = make_float4(xbv, yb, zb, 0.f);
        dist[2*p] = __float_as_uint(1e10f); dist[2*p+1] = __float_as_uint(1e10f);
    }
    if (tid < 2) swin[tid] = 0x7fffffff;
    if (tid >= 8 && tid < 32) swm[tid] = 0u;   // pad for full-warp redux
    __syncthreads();

    float4 c0 = spts[0];
    float cx = c0.x, cy = c0.y, cz = c0.z;

    for (int it = 0; it < NS; ++it) {
        if (tid == 0) {
            outxyz[(b*3 + 0)*NS + it] = cx;
            outxyz[(b*3 + 1)*NS + it] = cy;
            outxyz[(b*3 + 2)*NS + it] = cz;
            nxyz[((size_t)b*NS + it)*3 + 0] = cx;
            nxyz[((size_t)b*NS + it)*3 + 1] = cy;
            nxyz[((size_t)b*NS + it)*3 + 2] = cz;
        }
        unsigned long long cx2 = pk2(cx, cx);
        unsigned long long cy2 = pk2(cy, cy);
        unsigned long long cz2 = pk2(cz, cz);

#pragma unroll
        for (int p = 0; p < 16; ++p) {
            unsigned long long dx = f2sub(x2[p], cx2);
            unsigned long long dy = f2sub(y2[p], cy2);
            unsigned long long dz = f2sub(z2[p], cz2);
            // (dx*dx + dy*dy) + dz*dz -- lane-wise identical to scalar mul/add rounding
            unsigned long long s = f2add(f2add(f2mul(dx, dx), f2mul(dy, dy)), f2mul(dz, dz));
            unsigned slo, shi; upk2u(s, slo, shi);
            dist[2*p]   = min(dist[2*p],   slo);   // uint min == float min (nonneg)
            dist[2*p+1] = min(dist[2*p+1], shi);
        }
        unsigned key = 0u;
#pragma unroll
        for (int j = 0; j < 32; ++j) key = max(key, dist[j]);

        unsigned kmax = __reduce_max_sync(0xffffffffu, key);
        if (lane == 0) swm[wid] = kmax;
        __syncthreads();                               // b1: swm complete
        unsigned g = __reduce_max_sync(0xffffffffu, swm[lane]);  // every warp
        if (tid == 0) swin[(it + 1) & 1] = 0x7fffffff; // reset next slot
        if (key == g) {                                // rare: 1-2 threads
            int li = 0x7fffffff;
#pragma unroll
            for (int p = 15; p >= 0; --p) {            // lo overwrites hi -> first occurrence
                if (dist[2*p+1] == g) li = tid + (2*p+1) * 256;
                if (dist[2*p]   == g) li = tid + (2*p)   * 256;
            }
            atomicMin(&swin[it & 1], li);              // min over threads -> global first
        }
        __syncthreads();                               // b2: winner ready
        float4 cc = spts[swin[it & 1]];
        cx = cc.x; cy = cc.y; cz = cc.z;
    }
}

// ---------------- ball query: one warp per center ----------------
__global__ __launch_bounds__(256) void ball_kernel(const float* __restrict__ xyz,
                                                   const float* __restrict__ nxyz,
                                                   int* __restrict__ gidx)
{
    __shared__ int sbuf[8][32];
    int w = threadIdx.x >> 5, lane = threadIdx.x & 31;
    int gid = blockIdx.x * 8 + w;
    int b = gid >> 11, s = gid & 2047;
    const float* X = xyz + (size_t)b * 3 * NPTS;

    float cx = nxyz[gid*3], cy = nxyz[gid*3 + 1], cz = nxyz[gid*3 + 2];
    float cc = __fadd_rn(__fadd_rn(__fmul_rn(cx,cx), __fmul_rn(cy,cy)), __fmul_rn(cz,cz));
    const float R2 = (float)(0.1 * 0.1);

    int cnt = 0;
    for (int base = 0; base < NPTS; base += 32) {
        int n = base + lane;
        float px = X[n], py = X[NPTS + n], pz = X[2*NPTS + n];
        float pp  = __fadd_rn(__fadd_rn(__fmul_rn(px,px), __fmul_rn(py,py)), __fmul_rn(pz,pz));
        float dot = __fadd_rn(__fadd_rn(__fmul_rn(cx,px), __fmul_rn(cy,py)), __fmul_rn(cz,pz));
        float sqr = __fadd_rn(__fadd_rn(cc, pp), -__fmul_rn(2.f, dot));
        bool hit = (sqr <= R2);
        unsigned m = __ballot_sync(0xffffffffu, hit);
        if (m) {
            int rank = cnt + __popc(m & ((1u << lane) - 1u));
            if (hit && rank < 32) sbuf[w][rank] = n;
            cnt += __popc(m);
            if (cnt >= 32) break;
        }
    }
    __syncwarp();
    int first = sbuf[w][0];
    int my = (lane < cnt) ? sbuf[w][lane] : first;
    gidx[((size_t)(b*32 + lane))*2048 + s] = my;
}

// ---------------- gather + center-subtract + concat ----------------
__global__ __launch_bounds__(256) void gather_kernel(const float* __restrict__ xyz,
                                                     const float* __restrict__ pts,
                                                     const int* __restrict__ gidx,
                                                     const float* __restrict__ nxyz,
                                                     float* __restrict__ xin)
{
    int g = blockIdx.x * 256 + threadIdx.x;
    int s = g & 2047, k = (g >> 11) & 31, b = g >> 16;
    int id = gidx[((size_t)(b*32 + k))*2048 + s];
    const float* X = xyz + (size_t)b * 3 * NPTS;
    const float* P = pts + (size_t)b * 29 * NPTS;
    size_t ob = (size_t)b * 32 * MPB + (size_t)k * 2048 + s;
#pragma unroll
    for (int c = 0; c < 3; ++c)
        xin[ob + (size_t)c * MPB] = X[c*NPTS + id] - nxyz[((size_t)(b*2048 + s))*3 + c];
#pragma unroll
    for (int c = 0; c < 29; ++c)
        xin[ob + (size_t)(3 + c) * MPB] = P[c*NPTS + id];
}

// ---------------- conv v3: 256 pts/block, 8 pts/thread, fused stats ----------------
template<int CIN, bool ACT>
__global__ __launch_bounds__(256) void conv_kernel(const float* __restrict__ in,
                                                   const float* __restrict__ W,
                                                   const float* __restrict__ aff,
                                                   float* __restrict__ out,
                                                   float* __restrict__ ps,
                                                   float* __restrict__ pq)
{
    constexpr int CH = CIN / 8;
    __shared__ float sW[CIN][64];
    __shared__ float sX[2][8][256];
    __shared__ float sA[64], sD[64];
    int tid = threadIdx.x, lane = tid & 31, w = tid >> 5;
    int b = blockIdx.x >> 8, mblk = blockIdx.x & 255;
    const float* ip = in + (size_t)b * CIN * MPB + mblk * 256;

    for (int i = tid; i < CIN * 64; i += 256)
        sW[i >> 6][i & 63] = W[(i & 63) * CIN + (i >> 6)];
    if (ACT) for (int i = tid; i < CIN; i += 256) { sA[i] = aff[i]; sD[i] = aff[64 + i]; }

    float4 xa = *(const float4*)(ip + (size_t)w * MPB + lane * 4);
    float4 xb = *(const float4*)(ip + (size_t)w * MPB + 128 + lane * 4);
    float4 na, nb;
    if (CH > 1) {
        na = *(const float4*)(ip + (size_t)(8 + w) * MPB + lane * 4);
        nb = *(const float4*)(ip + (size_t)(8 + w) * MPB + 128 + lane * 4);
    }
    __syncthreads();
    {
        float4 va = xa, vb = xb;
        if (ACT) { float a = sA[w], d = sD[w];
            va.x = fmaxf(fmaf(a, va.x, d), 0.f); va.y = fmaxf(fmaf(a, va.y, d), 0.f);
            va.z = fmaxf(fmaf(a, va.z, d), 0.f); va.w = fmaxf(fmaf(a, va.w, d), 0.f);
            vb.x = fmaxf(fmaf(a, vb.x, d), 0.f); vb.y = fmaxf(fmaf(a, vb.y, d), 0.f);
            vb.z = fmaxf(fmaf(a, vb.z, d), 0.f); vb.w = fmaxf(fmaf(a, vb.w, d), 0.f); }
        *(float4*)&sX[0][w][lane * 4]       = va;
        *(float4*)&sX[0][w][128 + lane * 4] = vb;
    }
    __syncthreads();

    int og = w * 8;
    unsigned long long acc[4][8];
#pragma unroll
    for (int p = 0; p < 4; ++p)
#pragma unroll
        for (int j = 0; j < 8; ++j) acc[p][j] = 0ull;

    for (int k = 0; k < CH; ++k) {
#pragma unroll
        for (int cc = 0; cc < 8; ++cc) {
            int c = k * 8 + cc;
            float4 ua = *(const float4*)&sX[k & 1][cc][lane * 4];
            float4 ub = *(const float4*)&sX[k & 1][cc][128 + lane * 4];
            unsigned long long xp[8] = { pk2(ua.x, ua.x), pk2(ua.y, ua.y),
                                         pk2(ua.z, ua.z), pk2(ua.w, ua.w),
                                         pk2(ub.x, ub.x), pk2(ub.y, ub.y),
                                         pk2(ub.z, ub.z), pk2(ub.w, ub.w) };
            const double2* wp = (const double2*)&sW[c][og];
            double2 w0 = wp[0], w1 = wp[1];
            unsigned long long wq[4] = {
                __double_as_longlong(w0.x), __double_as_longlong(w0.y),
                __double_as_longlong(w1.x), __double_as_longlong(w1.y) };
#pragma unroll
            for (int p = 0; p < 4; ++p)
#pragma unroll
                for (int j = 0; j < 8; ++j)
                    acc[p][j] = f2fma(wq[p], xp[j], acc[p][j]);
        }
        if (k + 1 < CH) {
            float4 va = na, vb = nb;
            if (ACT) { int ch = (k + 1) * 8 + w; float a = sA[ch], d = sD[ch];
                va.x = fmaxf(fmaf(a, va.x, d), 0.f); va.y = fmaxf(fmaf(a, va.y, d), 0.f);
                va.z = fmaxf(fmaf(a, va.z, d), 0.f); va.w = fmaxf(fmaf(a, va.w, d), 0.f);
                vb.x = fmaxf(fmaf(a, vb.x, d), 0.f); vb.y = fmaxf(fmaf(a, vb.y, d), 0.f);
                vb.z = fmaxf(fmaf(a, vb.z, d), 0.f); vb.w = fmaxf(fmaf(a, vb.w, d), 0.f); }
            *(float4*)&sX[(k + 1) & 1][w][lane * 4]       = va;
            *(float4*)&sX[(k + 1) & 1][w][128 + lane * 4] = vb;
            if (k + 2 < CH) {
                na = *(const float4*)(ip + (size_t)((k + 2) * 8 + w) * MPB + lane * 4);
                nb = *(const float4*)(ip + (size_t)((k + 2) * 8 + w) * MPB + 128 + lane * 4);
            }
        }
        __syncthreads();
    }

    float* op = out + (size_t)b * 64 * MPB + mblk * 256;
    int pblk = b * 256 + mblk;
#pragma unroll
    for (int p = 0; p < 4; ++p) {
        float4 a0, a1, b0, b1;
        upk2(acc[p][0], a0.x, a1.x); upk2(acc[p][1], a0.y, a1.y);
        upk2(acc[p][2], a0.z, a1.z); upk2(acc[p][3], a0.w, a1.w);
        upk2(acc[p][4], b0.x, b1.x); upk2(acc[p][5], b0.y, b1.y);
        upk2(acc[p][6], b0.z, b1.z); upk2(acc[p][7], b0.w, b1.w);
        int o0 = og + 2*p, o1 = og + 2*p + 1;
        *(float4*)(op + (size_t)o0 * MPB + lane * 4)       = a0;
        *(float4*)(op + (size_t)o0 * MPB + 128 + lane * 4) = b0;
        *(float4*)(op + (size_t)o1 * MPB + lane * 4)       = a1;
        *(float4*)(op + (size_t)o1 * MPB + 128 + lane * 4) = b1;
        float s0 = (a0.x + a0.y + a0.z + a0.w) + (b0.x + b0.y + b0.z + b0.w);
        float q0 = (a0.x*a0.x + a0.y*a0.y + a0.z*a0.z + a0.w*a0.w)
                 + (b0.x*b0.x + b0.y*b0.y + b0.z*b0.z + b0.w*b0.w);
        float s1 = (a1.x + a1.y + a1.z + a1.w) + (b1.x + b1.y + b1.z + b1.w);
        float q1 = (a1.x*a1.x + a1.y*a1.y + a1.z*a1.z + a1.w*a1.w)
                 + (b1.x*b1.x + b1.y*b1.y + b1.z*b1.z + b1.w*b1.w);
#pragma unroll
        for (int off = 16; off; off >>= 1) {
            s0 += __shfl_xor_sync(0xffffffffu, s0, off);
            q0 += __shfl_xor_sync(0xffffffffu, q0, off);
            s1 += __shfl_xor_sync(0xffffffffu, s1, off);
            q1 += __shfl_xor_sync(0xffffffffu, q1, off);
        }
        if (lane == 0) {
            ps[o0 * NPB + pblk] = s0;  pq[o0 * NPB + pblk] = q0;
            ps[o1 * NPB + pblk] = s1;  pq[o1 * NPB + pblk] = q1;
        }
    }
}

// ---------------- stage-2 stats: NPB partials -> affine coeffs ----------------
__global__ __launch_bounds__(256) void statsfin2_kernel(const float* __restrict__ ps,
                                                        const float* __restrict__ pq,
                                                        const float* __restrict__ gam,
                                                        const float* __restrict__ bet,
                                                        float* __restrict__ aff)
{
    int o = blockIdx.x, tid = threadIdx.x;
    float s = 0.f, q = 0.f;
    for (int i = tid; i < NPB; i += 256) { s += ps[o*NPB + i]; q += pq[o*NPB + i]; }
    __shared__ float rs[256], rq[256];
    rs[tid] = s; rq[tid] = q;
    for (int off = 128; off; off >>= 1) {
        __syncthreads();
        if (tid < off) { rs[tid] += rs[tid + off]; rq[tid] += rq[tid + off]; }
    }
    if (tid == 0) {
        const float invn = 1.f / (float)(NB * MPB);
        float mean = rs[0] * invn;
        float var  = rq[0] * invn - mean * mean;
        float a = gam[o] * rsqrtf(var + 1e-5f);
        aff[o] = a;
        aff[64 + o] = bet[o] - a * mean;
    }
}

// ---------------- residual: x1 = relu(aff2(t2) + relu(aff0(y0))) ----------------
__global__ __launch_bounds__(256) void resid_kernel(const float* __restrict__ y0,
                                                    const float* __restrict__ t2,
                                                    const float* __restrict__ aff0,
                                                    const float* __restrict__ aff2,
                                                    float* __restrict__ x1)
{
    size_t i = (size_t)blockIdx.x * 256 + threadIdx.x;
    int c = (int)((i >> 14) & 63);
    float a0 = aff0[c], d0 = aff0[64+c], a2 = aff2[c], d2 = aff2[64+c];
    float4 y = ((const float4*)y0)[i];
    float4 t = ((const float4*)t2)[i];
    float4 r;
    r.x = fmaxf(fmaf(a2, t.x, d2) + fmaxf(fmaf(a0, y.x, d0), 0.f), 0.f);
    r.y = fmaxf(fmaf(a2, t.y, d2) + fmaxf(fmaf(a0, y.y, d0), 0.f), 0.f);
    r.z = fmaxf(fmaf(a2, t.z, d2) + fmaxf(fmaf(a0, y.z, d0), 0.f), 0.f);
    r.w = fmaxf(fmaf(a2, t.w, d2) + fmaxf(fmaf(a0, y.w, d0), 0.f), 0.f);
    ((float4*)x1)[i] = r;
}

// ---------------- final: feat = max_k relu(aff4(t4) + x1) ----------------
__global__ __launch_bounds__(256) void finalmax_kernel(const float* __restrict__ t4,
                                                       const float* __restrict__ x1,
                                                       const float* __restrict__ aff,
                                                       float* __restrict__ outf)
{
    int g = blockIdx.x * 256 + threadIdx.x;
    int s = g & 2047, o = (g >> 11) & 63, b = g >> 17;
    float a = aff[o], d = aff[64 + o];
    size_t base = (size_t)(b*64 + o) * MPB + s;
    const float* tp = t4 + base;
    const float* xp = x1 + base;
    float m = -1e30f;
#pragma unroll 8
    for (int k = 0; k < 32; ++k)
        m = fmaxf(m, fmaf(a, tp[(size_t)k*2048], d) + xp[(size_t)k*2048]);
    outf[g] = fmaxf(m, 0.f);
}

extern "C" void kernel_launch(void* const* d_in, const int* in_sizes, int n_in,
                              void* d_out, int out_size)
{
    (void)in_sizes; (void)n_in; (void)out_size;
    const float* xyz = (const float*)d_in[0];
    const float* pts = (const float*)d_in[1];
    const float* pw  = (const float*)d_in[2];
    const float* pg  = (const float*)d_in[3];
    const float* pb  = (const float*)d_in[4];
    const float* w1  = (const float*)d_in[5];
    const float* g1  = (const float*)d_in[6];
    const float* b1  = (const float*)d_in[7];
    const float* w2  = (const float*)d_in[8];
    const float* g2  = (const float*)d_in[9];
    const float* b2  = (const float*)d_in[10];

    float *y0, *t1, *t2, *x1, *nx, *ps, *pq, *aff; int* gi;
    cudaGetSymbolAddress((void**)&y0,  g_y0);
    cudaGetSymbolAddress((void**)&t1,  g_t1);
    cudaGetSymbolAddress((void**)&t2,  g_t2);
    cudaGetSymbolAddress((void**)&x1,  g_x1);
    cudaGetSymbolAddress((void**)&nx,  g_nxyz);
    cudaGetSymbolAddress((void**)&gi,  g_idx);
    cudaGetSymbolAddress((void**)&ps,  g_ps);
    cudaGetSymbolAddress((void**)&pq,  g_pq);
    cudaGetSymbolAddress((void**)&aff, g_aff);
    float* out = (float*)d_out;

    cudaFuncSetAttribute(fps_kernel, cudaFuncAttributeMaxDynamicSharedMemorySize,
                         NPTS * (int)sizeof(float4));

    fps_kernel<<<NB, 256, NPTS * sizeof(float4)>>>(xyz, out, nx);
    ball_kernel<<<1024, 256>>>(xyz, nx, gi);
    gather_kernel<<<1024, 256>>>(xyz, pts, gi, nx, t2);

    conv_kernel<32, false><<<1024, 256>>>(t2, pw, nullptr, y0, ps, pq);
    statsfin2_kernel<<<64, 256>>>(ps, pq, pg, pb, aff);

    conv_kernel<64, true><<<1024, 256>>>(y0, w1, aff, t1, ps, pq);
    statsfin2_kernel<<<64, 256>>>(ps, pq, g1, b1, aff + 128);

    conv_kernel<64, true><<<1024, 256>>>(t1, w2, aff + 128, t2, ps, pq);
    statsfin2_kernel<<<64, 256>>>(ps, pq, g2, b2, aff + 256);

    resid_kernel<<<16384, 256>>>(y0, t2, aff, aff + 256, x1);

    conv_kernel<64, false><<<1024, 256>>>(x1, w1 + 4096, nullptr, t1, ps, pq);
    statsfin2_kernel<<<64, 256>>>(ps, pq, g1 + 64, b1 + 64, aff + 384);

    conv_kernel<64, true><<<1024, 256>>>(t1, w2 + 4096, aff + 384, t2, ps, pq);
    statsfin2_kernel<<<64, 256>>>(ps, pq, g2 + 64, b2 + 64, aff + 512);

    finalmax_kernel<<<2048, 256>>>(t2, x1, aff + 512, out + NB*3*NS);
}